// round 7
// baseline (speedup 1.0000x reference)
#include <cuda_runtime.h>
#include <cstdint>

#define DIMS   256
#define BATCH  2048
#define NPAIR  32896              // 256*257/2 upper-triangle pairs
#define NROWS  33280              // 260 tiles * 128 rows (pairs + c2 + c1 + pad)
#define BM     128
#define BN     128

// ---- device scratch (allocation-free) ----
// A in MMA-fragment order: word = ((ptile*32 + ks)*32 + lane)*4 + r
//   ptile = p>>4, ks = k>>3; lane = (p&7)*4 + (k&3);
//   r = ((k&7)>>2)*2 + ((p&15)>>3)
__device__ float    g_c3p[NROWS * DIMS];         // 34 MB, tf32-pre-rounded
__device__ uint32_t g_pairIdx[NROWS];            // (i<<16)|j per row
// B in fragment order: word = ((ng*16 + kp)*32 + lane)*4 + r
//   ng = b>>3, kp = k>>4; lane = (b&7)*4 + (k&3); r = ((k>>3)&1)*2 + ((k&7)>>2)
__device__ float    g_relf[BATCH * DIMS];        // 2 MB, tf32-pre-rounded
__device__ float    g_relT[(DIMS + 1) * BATCH];  // rel^T exact; row 256 = 1.0

static __device__ __forceinline__ float f2tf32f(float f) {
    uint32_t r;
    asm("cvt.rna.tf32.f32 %0, %1;" : "=r"(r) : "f"(f));
    return __uint_as_float(r);
}

#define MMA_TF32(C, A0, A1, A2, A3, B0, B1)                                   \
    asm volatile(                                                             \
        "mma.sync.aligned.m16n8k8.row.col.f32.tf32.tf32.f32 "                 \
        "{%0,%1,%2,%3}, {%4,%5,%6,%7}, {%8,%9}, {%0,%1,%2,%3};"               \
        : "+f"((C)[0]), "+f"((C)[1]), "+f"((C)[2]), "+f"((C)[3])              \
        : "r"(A0), "r"(A1), "r"(A2), "r"(A3), "r"(B0), "r"(B1))

// ---------------------------------------------------------------------------
// Prep: g_relf (fragment order, tf32) + g_relT (exact weights, +ones row)
// ---------------------------------------------------------------------------
__global__ void prep_rel_kernel(const float* __restrict__ x,
                                const float* __restrict__ offsets) {
    int idx = blockIdx.x * blockDim.x + threadIdx.x;   // k*BATCH + b
    int k = idx / BATCH;
    int b = idx % BATCH;
    if (k < DIMS) {
        float r = x[b * DIMS + k] - offsets[k];
        g_relT[idx] = r;
        int ng = b >> 3, kp = k >> 4;
        int lane = (b & 7) * 4 + (k & 3);
        int rr = (((k >> 3) & 1) << 1) | ((k & 7) >> 2);
        ((uint32_t*)g_relf)[((ng * 16 + kp) * 32 + lane) * 4 + rr] =
            __float_as_uint(f2tf32f(r));
    } else {
        g_relT[idx] = 1.0f;
    }
}

__global__ void init_out_kernel(const float* __restrict__ c0p,
                                float* __restrict__ out) {
    int b = blockIdx.x * blockDim.x + threadIdx.x;
    if (b < BATCH) out[b] = c0p[0];
}

// ---------------------------------------------------------------------------
// Pack: symmetrize c3 (+c2, +c1, +pad) straight into A-fragment order.
// Block (j, i-slot) x 64 threads; thread t covers k = 4t..4t+3.
// ---------------------------------------------------------------------------
__global__ void pack_kernel(const float* __restrict__ c3,
                            const float* __restrict__ c2,
                            const float* __restrict__ c1) {
    int j = blockIdx.x, i = blockIdx.y, t = threadIdx.x;
    int p;
    float4 v;
    uint32_t pidx;
    if (i < 256) {
        if (j < i) return;
        p = i * 256 - (i * (i - 1)) / 2 + (j - i);
        v = *(const float4*)(c3 + ((size_t)(i * 256 + j)) * DIMS + t * 4);
        if (i != j) {
            float4 w = *(const float4*)(c3 + ((size_t)(j * 256 + i)) * DIMS + t * 4);
            v.x += w.x; v.y += w.y; v.z += w.z; v.w += w.w;
        }
        pidx = ((uint32_t)i << 16) | (uint32_t)j;
    } else if (i == 256) {                       // c2 rows: weight r_j * 1
        p = NPAIR + j;
        v = *(const float4*)(c2 + (size_t)j * DIMS + t * 4);
        pidx = (256u << 16) | (uint32_t)j;
    } else {                                     // i == 257
        if (j == 0) {                            // c1 row: weight 1 * 1
            p = NPAIR + 256;
            v = *(const float4*)(c1 + t * 4);
        } else if (j < 128) {                    // zero pad
            p = NPAIR + 256 + j;
            v = make_float4(0.f, 0.f, 0.f, 0.f);
        } else return;
        pidx = (256u << 16) | 256u;
    }
    // scatter into fragment layout: k = 4t + e, e = 0..3
    int ptile = p >> 4, prow = p & 15;
    int gg = prow & 7, half = prow >> 3;
    int ks = t >> 1;                  // (4t)>>3
    int kh = t & 1;                   // ((4t)&7)>>2
    int rr = kh * 2 + half;
    uint32_t* W = (uint32_t*)g_c3p;
    size_t basew = (((size_t)ptile * 32 + ks) * 32 + gg * 4) * 4 + rr;
    W[basew + 0]  = __float_as_uint(f2tf32f(v.x));
    W[basew + 4]  = __float_as_uint(f2tf32f(v.y));
    W[basew + 8]  = __float_as_uint(f2tf32f(v.z));
    W[basew + 12] = __float_as_uint(f2tf32f(v.w));
    if (t == 0) g_pairIdx[p] = pidx;
}

// ---------------------------------------------------------------------------
// Main fused GEMM: direct fragment LDG from GMEM (no SMEM operands, no
// mainloop barriers), mma.sync tf32, fused weighted reduction.
// 16 pipeline steps of k16 each; double-buffered register prefetch.
// ---------------------------------------------------------------------------
__global__ void __launch_bounds__(256) taylor_mma_kernel(
    float* __restrict__ out) {

    __shared__ float sred[BN];

    const int tid  = threadIdx.x;
    const int lane = tid & 31, wid = tid >> 5;
    const int warpM = wid & 3, warpN = wid >> 2;
    const int g = lane >> 2, tig = lane & 3;
    const int p0 = blockIdx.x * BM;
    const int b0 = blockIdx.y * BN;

    if (tid < BN) sred[tid] = 0.f;

    // fragment base pointers (uint4 granularity)
    const uint4* Af = (const uint4*)g_c3p;
    const uint4* Bf = (const uint4*)g_relf;
    const uint4* aptr[2];
#pragma unroll
    for (int ms = 0; ms < 2; ++ms)
        aptr[ms] = Af + (size_t)((p0 >> 4) + warpM * 2 + ms) * 1024 + lane;
    const uint4* bptr[8];
#pragma unroll
    for (int nsl = 0; nsl < 8; ++nsl)
        bptr[nsl] = Bf + (size_t)((b0 >> 3) + warpN * 8 + nsl) * 512 + lane;

    float acc[2][8][4];
#pragma unroll
    for (int m = 0; m < 2; m++)
#pragma unroll
        for (int n = 0; n < 8; n++)
#pragma unroll
            for (int r = 0; r < 4; r++) acc[m][n][r] = 0.f;

    uint4 A0[2][2], B0b[8], A1[2][2], B1b[8];

#define LD_STEP(s, AB, BB)                                                    \
    do {                                                                      \
        _Pragma("unroll")                                                     \
        for (int ms = 0; ms < 2; ++ms) {                                      \
            (AB)[ms][0] = __ldcs(aptr[ms] + (2 * (s) + 0) * 32);              \
            (AB)[ms][1] = __ldcs(aptr[ms] + (2 * (s) + 1) * 32);              \
        }                                                                     \
        _Pragma("unroll")                                                     \
        for (int nsl = 0; nsl < 8; ++nsl)                                     \
            (BB)[nsl] = __ldg(bptr[nsl] + (s) * 32);                          \
    } while (0)

#define MMA_STEP(AB, BB)                                                      \
    do {                                                                      \
        _Pragma("unroll")                                                     \
        for (int nsl = 0; nsl < 8; ++nsl) {                                   \
            _Pragma("unroll")                                                 \
            for (int ms = 0; ms < 2; ++ms) {                                  \
                MMA_TF32(acc[ms][nsl], (AB)[ms][0].x, (AB)[ms][0].y,          \
                         (AB)[ms][0].z, (AB)[ms][0].w,                        \
                         (BB)[nsl].x, (BB)[nsl].y);                           \
                MMA_TF32(acc[ms][nsl], (AB)[ms][1].x, (AB)[ms][1].y,          \
                         (AB)[ms][1].z, (AB)[ms][1].w,                        \
                         (BB)[nsl].z, (BB)[nsl].w);                           \
            }                                                                 \
        }                                                                     \
    } while (0)

    LD_STEP(0, A0, B0b);
#pragma unroll
    for (int sp = 0; sp < 8; ++sp) {
        LD_STEP(2 * sp + 1, A1, B1b);
        MMA_STEP(A0, B0b);
        if (sp < 7) LD_STEP(2 * sp + 2, A0, B0b);
        MMA_STEP(A1, B1b);
    }

    __syncthreads();   // sred init visible before epilogue atomics

    // ---- epilogue: sred[col] += sum_m D[m,col] * r_i(m)[b] * r_j(m)[b] ----
    const float* wi[2][2];
    const float* wj[2][2];
#pragma unroll
    for (int msl = 0; msl < 2; ++msl)
#pragma unroll
        for (int h = 0; h < 2; ++h) {
            int rloc = warpM * 32 + msl * 16 + h * 8 + g;
            uint32_t pij = g_pairIdx[p0 + rloc];
            wi[msl][h] = g_relT + (size_t)(pij >> 16) * BATCH + b0;
            wj[msl][h] = g_relT + (size_t)(pij & 0xFFFF) * BATCH + b0;
        }

#pragma unroll
    for (int nsl = 0; nsl < 8; ++nsl) {
        const int coln = warpN * 64 + nsl * 8 + tig * 2;
        float s0 = 0.f, s1 = 0.f;
#pragma unroll
        for (int msl = 0; msl < 2; ++msl) {
            float2 a = *(const float2*)(wi[msl][0] + coln);
            float2 b = *(const float2*)(wj[msl][0] + coln);
            s0 += acc[msl][nsl][0] * a.x * b.x;
            s1 += acc[msl][nsl][1] * a.y * b.y;
            a = *(const float2*)(wi[msl][1] + coln);
            b = *(const float2*)(wj[msl][1] + coln);
            s0 += acc[msl][nsl][2] * a.x * b.x;
            s1 += acc[msl][nsl][3] * a.y * b.y;
        }
#pragma unroll
        for (int o = 4; o <= 16; o <<= 1) {
            s0 += __shfl_xor_sync(0xFFFFFFFFu, s0, o);
            s1 += __shfl_xor_sync(0xFFFFFFFFu, s1, o);
        }
        if (g == 0) {
            atomicAdd(&sred[coln],     s0);
            atomicAdd(&sred[coln + 1], s1);
        }
    }
    __syncthreads();

    if (tid < BN) atomicAdd(out + b0 + tid, sred[tid]);
}

// ---------------------------------------------------------------------------
extern "C" void kernel_launch(void* const* d_in, const int* in_sizes, int n_in,
                              void* d_out, int out_size) {
    const float* x       = (const float*)d_in[0];
    const float* offsets = (const float*)d_in[1];
    const float* coeff0  = (const float*)d_in[2];
    const float* coeff1  = (const float*)d_in[3];
    const float* coeff2  = (const float*)d_in[4];
    const float* coeff3  = (const float*)d_in[5];
    float* out = (float*)d_out;

    prep_rel_kernel<<<((DIMS + 1) * BATCH) / 256, 256>>>(x, offsets);
    init_out_kernel<<<BATCH / 256, 256>>>(coeff0, out);

    dim3 pgrid(256, 258);
    pack_kernel<<<pgrid, 64>>>(coeff3, coeff2, coeff1);

    dim3 grid(NROWS / BM, BATCH / BN);   // (260, 16)
    taylor_mma_kernel<<<grid, 256>>>(out);
}

// round 8
// speedup vs baseline: 1.8053x; 1.8053x over previous
#include <cuda_runtime.h>
#include <cstdint>

#define DIMS   256
#define BATCH  2048
#define NPAIR  32896              // 256*257/2 upper-triangle pairs
#define NROWS  33280              // 260 tiles * 128 rows
#define BM     128
#define BN     256
#define KC     32
#define NCHUNK 8
#define STAGES 4
#define STAGE_BYTES (BM * KC * 4)               // 16 KB (A only)
#define SMEM_BYTES  (STAGES * STAGE_BYTES + BN * 4)

// ---- device scratch (allocation-free) ----
__device__ float    g_c3p[NROWS * DIMS];         // 34 MB packed A, row-major, tf32-rounded
__device__ uint32_t g_pairIdx[NROWS];            // (i<<16)|j per row
// B fragment-major (verified in R7): word = ((ng*16 + kp)*32 + lane)*4 + r
//   ng=b>>3, kp=k>>4, lane=(b&7)*4+(k&3), r=((k>>3)&1)*2+((k&7)>>2)
__device__ float    g_relf[BATCH * DIMS];        // 2 MB, tf32-rounded
__device__ float    g_relT[(DIMS + 1) * BATCH];  // rel^T exact; row 256 = 1.0

static __device__ __forceinline__ float f2tf32f(float f) {
    uint32_t r;
    asm("cvt.rna.tf32.f32 %0, %1;" : "=r"(r) : "f"(f));
    return __uint_as_float(r);
}

#define MMA_TF32(C, A0, A1, A2, A3, B0, B1)                                   \
    asm volatile(                                                             \
        "mma.sync.aligned.m16n8k8.row.col.f32.tf32.tf32.f32 "                 \
        "{%0,%1,%2,%3}, {%4,%5,%6,%7}, {%8,%9}, {%0,%1,%2,%3};"               \
        : "+f"((C)[0]), "+f"((C)[1]), "+f"((C)[2]), "+f"((C)[3])              \
        : "r"(A0), "r"(A1), "r"(A2), "r"(A3), "r"(B0), "r"(B1))

#define LDSM4(R, addr)                                                        \
    asm volatile("ldmatrix.sync.aligned.m8n8.x4.shared.b16 {%0,%1,%2,%3}, [%4];" \
        : "=r"((R)[0]), "=r"((R)[1]), "=r"((R)[2]), "=r"((R)[3])              \
        : "r"(addr))

static __device__ __forceinline__ void cp16(uint32_t dst, const void* gsrc) {
    asm volatile("cp.async.cg.shared.global [%0], [%1], 16;"
                 :: "r"(dst), "l"(gsrc) : "memory");
}
#define CP_COMMIT() asm volatile("cp.async.commit_group;" ::: "memory")
#define CP_WAIT2()  asm volatile("cp.async.wait_group 2;" ::: "memory")

static __device__ __forceinline__ uint32_t smem_u32(const void* p) {
    uint32_t a;
    asm("{ .reg .u64 t; cvta.to.shared.u64 t, %1; cvt.u32.u64 %0, t; }" : "=r"(a) : "l"(p));
    return a;
}

// ---------------------------------------------------------------------------
__global__ void prep_rel_kernel(const float* __restrict__ x,
                                const float* __restrict__ offsets) {
    int idx = blockIdx.x * blockDim.x + threadIdx.x;   // k*BATCH + b
    int k = idx / BATCH;
    int b = idx % BATCH;
    if (k < DIMS) {
        float r = x[b * DIMS + k] - offsets[k];
        g_relT[idx] = r;
        int ng = b >> 3, kp = k >> 4;
        int lane = (b & 7) * 4 + (k & 3);
        int rr = (((k >> 3) & 1) << 1) | ((k & 7) >> 2);
        ((uint32_t*)g_relf)[((ng * 16 + kp) * 32 + lane) * 4 + rr] =
            __float_as_uint(f2tf32f(r));
    } else {
        g_relT[idx] = 1.0f;
    }
}

__global__ void init_out_kernel(const float* __restrict__ c0p,
                                float* __restrict__ out) {
    int b = blockIdx.x * blockDim.x + threadIdx.x;
    if (b < BATCH) out[b] = c0p[0];
}

// ---------------------------------------------------------------------------
// Pack (coalesced, round-6 form): row-major symmetrized A + pair index table.
// ---------------------------------------------------------------------------
__global__ void pack_kernel(const float* __restrict__ c3,
                            const float* __restrict__ c2,
                            const float* __restrict__ c1) {
    int j = blockIdx.x, i = blockIdx.y, t = threadIdx.x;
    int p;
    float4 v;
    uint32_t pidx;
    if (i < 256) {
        if (j < i) return;
        p = i * 256 - (i * (i - 1)) / 2 + (j - i);
        v = *(const float4*)(c3 + ((size_t)(i * 256 + j)) * DIMS + t * 4);
        if (i != j) {
            float4 w = *(const float4*)(c3 + ((size_t)(j * 256 + i)) * DIMS + t * 4);
            v.x += w.x; v.y += w.y; v.z += w.z; v.w += w.w;
        }
        pidx = ((uint32_t)i << 16) | (uint32_t)j;
    } else if (i == 256) {
        p = NPAIR + j;
        v = *(const float4*)(c2 + (size_t)j * DIMS + t * 4);
        pidx = (256u << 16) | (uint32_t)j;
    } else {
        if (j == 0) {
            p = NPAIR + 256;
            v = *(const float4*)(c1 + t * 4);
        } else if (j < 128) {
            p = NPAIR + 256 + j;
            v = make_float4(0.f, 0.f, 0.f, 0.f);
        } else return;
        pidx = (256u << 16) | 256u;
    }
    v.x = f2tf32f(v.x); v.y = f2tf32f(v.y); v.z = f2tf32f(v.z); v.w = f2tf32f(v.w);
    *(float4*)(g_c3p + (size_t)p * DIMS + t * 4) = v;
    if (t == 0) g_pairIdx[p] = pidx;
}

// ---------------------------------------------------------------------------
// Main: A via cp.async(4-stage)+LDSM, B direct GMEM fragments (dbl-buffered),
// 8 warps = 2M x 4N of 64x64 tiles, one barrier per chunk.
// ---------------------------------------------------------------------------
__global__ void __launch_bounds__(256) taylor_mma_kernel(
    float* __restrict__ out) {

    extern __shared__ char smem[];
    const uint32_t sb = smem_u32(smem);
    float* sred = (float*)(smem + STAGES * STAGE_BYTES);

    const int tid  = threadIdx.x;
    const int lane = tid & 31, wid = tid >> 5;
    const int warpM = wid & 1, warpN = wid >> 1;   // 2 x 4 warps
    const int g = lane >> 2, tig = lane & 3;
    const int p0 = blockIdx.x * BM;
    const int b0 = blockIdx.y * BN;

    sred[tid] = 0.f;                                // BN == blockDim == 256

    // ---- A cp.async coords: 4 x 16B per thread per chunk ----
    const float* Ag = g_c3p + (size_t)p0 * DIMS;
    uint32_t cpdst[4];
    const float* cpsrc[4];
#pragma unroll
    for (int it = 0; it < 4; it++) {
        int idx = tid + it * 256;
        int row = idx >> 3, seg = idx & 7;
        cpdst[it] = row * 128 + ((seg ^ (row & 7)) << 4);
        cpsrc[it] = Ag + (size_t)row * DIMS + seg * 4;
    }
    auto cp_chunk = [&](int c, int stage) {
        const uint32_t s = sb + stage * STAGE_BYTES;
        const int k0 = c * KC;
#pragma unroll
        for (int it = 0; it < 4; it++)
            cp16(s + cpdst[it], cpsrc[it] + k0);
    };

    // ---- B fragment pointer (uint4 granularity) ----
    const uint4* bptr = (const uint4*)g_relf
                      + ((size_t)(b0 >> 3) + warpN * 8) * 512 + lane;

    // ---- LDSM per-msl addressing ----
    int aoff[4], axor[4];
#pragma unroll
    for (int msl = 0; msl < 4; msl++) {
        int rowA = warpM * 64 + msl * 16 + ((lane >> 3) & 1) * 8 + (lane & 7);
        aoff[msl] = rowA * 128;
        axor[msl] = rowA & 7;
    }
    const int kcA = (lane >> 4) & 1;

    float acc[4][8][4];
#pragma unroll
    for (int m = 0; m < 4; m++)
#pragma unroll
        for (int n = 0; n < 8; n++)
#pragma unroll
            for (int r = 0; r < 4; r++) acc[m][n][r] = 0.f;

    uint4 Bb0[8], Bb1[8];

    // prologue
    cp_chunk(0, 0); CP_COMMIT();
    cp_chunk(1, 1); CP_COMMIT();
    cp_chunk(2, 2); CP_COMMIT();
#pragma unroll
    for (int nsl = 0; nsl < 8; nsl++) Bb0[nsl] = __ldg(bptr + nsl * 512);

#define COMPUTE_KP(As, KSBASE, BB)                                            \
    do {                                                                      \
        _Pragma("unroll")                                                     \
        for (int ks2 = 0; ks2 < 2; ++ks2) {                                   \
            const int ks = (KSBASE) + ks2;                                    \
            uint32_t a[4][4];                                                 \
            _Pragma("unroll")                                                 \
            for (int msl = 0; msl < 4; ++msl)                                 \
                LDSM4(a[msl], (As) + aoff[msl] +                              \
                      ((((ks << 1) | kcA) ^ axor[msl]) << 4));                \
            _Pragma("unroll")                                                 \
            for (int nsl = 0; nsl < 8; ++nsl) {                               \
                uint32_t b0v = ks2 ? (BB)[nsl].z : (BB)[nsl].x;               \
                uint32_t b1v = ks2 ? (BB)[nsl].w : (BB)[nsl].y;               \
                _Pragma("unroll")                                             \
                for (int msl = 0; msl < 4; ++msl)                             \
                    MMA_TF32(acc[msl][nsl], a[msl][0], a[msl][1],             \
                             a[msl][2], a[msl][3], b0v, b1v);                 \
            }                                                                 \
        }                                                                     \
    } while (0)

    for (int cc = 0; cc < NCHUNK; ++cc) {
        CP_WAIT2();
        __syncthreads();                      // stage cc ready; stage (cc-1) free
        if (cc + 3 < NCHUNK) cp_chunk(cc + 3, (cc + 3) & 3);
        CP_COMMIT();

        const uint32_t As = sb + (cc & 3) * STAGE_BYTES;
        const int s0 = 2 * cc;

        // kp = 0: prefetch B for kp=1, compute with Bb0
#pragma unroll
        for (int nsl = 0; nsl < 8; nsl++)
            Bb1[nsl] = __ldg(bptr + nsl * 512 + (s0 + 1) * 32);
        COMPUTE_KP(As, 0, Bb0);

        // kp = 1: prefetch B for next chunk kp=0, compute with Bb1
        if (s0 + 2 < 16) {
#pragma unroll
            for (int nsl = 0; nsl < 8; nsl++)
                Bb0[nsl] = __ldg(bptr + nsl * 512 + (s0 + 2) * 32);
        }
        COMPUTE_KP(As, 2, Bb1);
    }

    // ---- epilogue: sred[col] += sum_m D[m,col] * r_i(m)[b] * r_j(m)[b] ----
    const float* wi[4][2];
    const float* wj[4][2];
#pragma unroll
    for (int msl = 0; msl < 4; ++msl)
#pragma unroll
        for (int h = 0; h < 2; ++h) {
            int rloc = warpM * 64 + msl * 16 + h * 8 + g;
            uint32_t pij = g_pairIdx[p0 + rloc];
            wi[msl][h] = g_relT + (size_t)(pij >> 16) * BATCH + b0;
            wj[msl][h] = g_relT + (size_t)(pij & 0xFFFF) * BATCH + b0;
        }

#pragma unroll
    for (int nsl = 0; nsl < 8; ++nsl) {
        const int coln = warpN * 64 + nsl * 8 + tig * 2;
        float s0 = 0.f, s1 = 0.f;
#pragma unroll
        for (int msl = 0; msl < 4; ++msl) {
#pragma unroll
            for (int h = 0; h < 2; ++h) {
                float2 a = *(const float2*)(wi[msl][h] + coln);
                float2 b = *(const float2*)(wj[msl][h] + coln);
                s0 += acc[msl][nsl][2 * h]     * a.x * b.x;
                s1 += acc[msl][nsl][2 * h + 1] * a.y * b.y;
            }
        }
#pragma unroll
        for (int o = 4; o <= 16; o <<= 1) {
            s0 += __shfl_xor_sync(0xFFFFFFFFu, s0, o);
            s1 += __shfl_xor_sync(0xFFFFFFFFu, s1, o);
        }
        if (g == 0) {
            atomicAdd(&sred[coln],     s0);
            atomicAdd(&sred[coln + 1], s1);
        }
    }
    __syncthreads();

    atomicAdd(out + b0 + tid, sred[tid]);
}

// ---------------------------------------------------------------------------
extern "C" void kernel_launch(void* const* d_in, const int* in_sizes, int n_in,
                              void* d_out, int out_size) {
    const float* x       = (const float*)d_in[0];
    const float* offsets = (const float*)d_in[1];
    const float* coeff0  = (const float*)d_in[2];
    const float* coeff1  = (const float*)d_in[3];
    const float* coeff2  = (const float*)d_in[4];
    const float* coeff3  = (const float*)d_in[5];
    float* out = (float*)d_out;

    cudaFuncSetAttribute(taylor_mma_kernel,
                         cudaFuncAttributeMaxDynamicSharedMemorySize, SMEM_BYTES);

    prep_rel_kernel<<<((DIMS + 1) * BATCH) / 256, 256>>>(x, offsets);
    init_out_kernel<<<BATCH / 256, 256>>>(coeff0, out);

    dim3 pgrid(256, 258);
    pack_kernel<<<pgrid, 64>>>(coeff3, coeff2, coeff1);

    dim3 grid(NROWS / BM, BATCH / BN);   // (260, 8)
    taylor_mma_kernel<<<grid, 256, SMEM_BYTES>>>(out);
}

// round 9
// speedup vs baseline: 1.8627x; 1.0318x over previous
#include <cuda_runtime.h>
#include <cstdint>

#define DIMS   256
#define BATCH  2048
#define NPAIR  32896              // 256*257/2 upper-triangle pairs
#define NROWS  33280              // 260 tiles * 128 rows
#define BM     128
#define BN     256
#define KC     32
#define NCHUNK 8
#define STAGES 4
#define THREADS 512
#define STAGE_BYTES (BM * KC * 4)               // 16 KB (A only)
#define SMEM_BYTES  (STAGES * STAGE_BYTES + BN * 4)

// ---- device scratch (allocation-free) ----
__device__ float    g_c3p[NROWS * DIMS];         // 34 MB packed A, row-major, tf32-rounded
__device__ uint32_t g_pairIdx[NROWS];            // (i<<16)|j per row
// B fragment-major: word = ((ng*16 + kp)*32 + lane)*4 + r
//   ng=b>>3, kp=k>>4, lane=(b&7)*4+(k&3), r=((k>>3)&1)*2+((k&7)>>2)
__device__ float    g_relf[BATCH * DIMS];        // 2 MB, tf32-rounded
__device__ float    g_relT[(DIMS + 1) * BATCH];  // rel^T exact; row 256 = 1.0

static __device__ __forceinline__ float f2tf32f(float f) {
    uint32_t r;
    asm("cvt.rna.tf32.f32 %0, %1;" : "=r"(r) : "f"(f));
    return __uint_as_float(r);
}

#define MMA_TF32(C, A0, A1, A2, A3, B0, B1)                                   \
    asm volatile(                                                             \
        "mma.sync.aligned.m16n8k8.row.col.f32.tf32.tf32.f32 "                 \
        "{%0,%1,%2,%3}, {%4,%5,%6,%7}, {%8,%9}, {%0,%1,%2,%3};"               \
        : "+f"((C)[0]), "+f"((C)[1]), "+f"((C)[2]), "+f"((C)[3])              \
        : "r"(A0), "r"(A1), "r"(A2), "r"(A3), "r"(B0), "r"(B1))

#define LDSM4(R, addr)                                                        \
    asm volatile("ldmatrix.sync.aligned.m8n8.x4.shared.b16 {%0,%1,%2,%3}, [%4];" \
        : "=r"((R)[0]), "=r"((R)[1]), "=r"((R)[2]), "=r"((R)[3])              \
        : "r"(addr))

static __device__ __forceinline__ void cp16(uint32_t dst, const void* gsrc) {
    asm volatile("cp.async.cg.shared.global [%0], [%1], 16;"
                 :: "r"(dst), "l"(gsrc) : "memory");
}
#define CP_COMMIT() asm volatile("cp.async.commit_group;" ::: "memory")
#define CP_WAIT2()  asm volatile("cp.async.wait_group 2;" ::: "memory")

static __device__ __forceinline__ uint32_t smem_u32(const void* p) {
    uint32_t a;
    asm("{ .reg .u64 t; cvta.to.shared.u64 t, %1; cvt.u32.u64 %0, t; }" : "=r"(a) : "l"(p));
    return a;
}

// ---------------------------------------------------------------------------
__global__ void prep_rel_kernel(const float* __restrict__ x,
                                const float* __restrict__ offsets) {
    int idx = blockIdx.x * blockDim.x + threadIdx.x;   // k*BATCH + b
    int k = idx / BATCH;
    int b = idx % BATCH;
    if (k < DIMS) {
        float r = x[b * DIMS + k] - offsets[k];
        g_relT[idx] = r;
        int ng = b >> 3, kp = k >> 4;
        int lane = (b & 7) * 4 + (k & 3);
        int rr = (((k >> 3) & 1) << 1) | ((k & 7) >> 2);
        ((uint32_t*)g_relf)[((ng * 16 + kp) * 32 + lane) * 4 + rr] =
            __float_as_uint(f2tf32f(r));
    } else {
        g_relT[idx] = 1.0f;
    }
}

__global__ void init_out_kernel(const float* __restrict__ c0p,
                                float* __restrict__ out) {
    int b = blockIdx.x * blockDim.x + threadIdx.x;
    if (b < BATCH) out[b] = c0p[0];
}

// ---------------------------------------------------------------------------
// Pack (coalesced): row-major symmetrized A + pair index table.
// ---------------------------------------------------------------------------
__global__ void pack_kernel(const float* __restrict__ c3,
                            const float* __restrict__ c2,
                            const float* __restrict__ c1) {
    int j = blockIdx.x, i = blockIdx.y, t = threadIdx.x;
    int p;
    float4 v;
    uint32_t pidx;
    if (i < 256) {
        if (j < i) return;
        p = i * 256 - (i * (i - 1)) / 2 + (j - i);
        v = *(const float4*)(c3 + ((size_t)(i * 256 + j)) * DIMS + t * 4);
        if (i != j) {
            float4 w = *(const float4*)(c3 + ((size_t)(j * 256 + i)) * DIMS + t * 4);
            v.x += w.x; v.y += w.y; v.z += w.z; v.w += w.w;
        }
        pidx = ((uint32_t)i << 16) | (uint32_t)j;
    } else if (i == 256) {
        p = NPAIR + j;
        v = *(const float4*)(c2 + (size_t)j * DIMS + t * 4);
        pidx = (256u << 16) | (uint32_t)j;
    } else {
        if (j == 0) {
            p = NPAIR + 256;
            v = *(const float4*)(c1 + t * 4);
        } else if (j < 128) {
            p = NPAIR + 256 + j;
            v = make_float4(0.f, 0.f, 0.f, 0.f);
        } else return;
        pidx = (256u << 16) | 256u;
    }
    v.x = f2tf32f(v.x); v.y = f2tf32f(v.y); v.z = f2tf32f(v.z); v.w = f2tf32f(v.w);
    *(float4*)(g_c3p + (size_t)p * DIMS + t * 4) = v;
    if (t == 0) g_pairIdx[p] = pidx;
}

// ---------------------------------------------------------------------------
// Main: 512 threads, 16 warps = 2M x 8N of 64x32 tiles.
// A via cp.async(4-stage)+LDSM, B direct GMEM fragments, 1 barrier/chunk.
// ---------------------------------------------------------------------------
__global__ void __launch_bounds__(THREADS) taylor_mma_kernel(
    float* __restrict__ out) {

    extern __shared__ char smem[];
    const uint32_t sb = smem_u32(smem);
    float* sred = (float*)(smem + STAGES * STAGE_BYTES);

    const int tid  = threadIdx.x;
    const int lane = tid & 31, wid = tid >> 5;
    const int warpM = wid & 1, warpN = wid >> 1;   // 2 x 8 warps
    const int g = lane >> 2, tig = lane & 3;
    const int p0 = blockIdx.x * BM;
    const int b0 = blockIdx.y * BN;

    if (tid < BN) sred[tid] = 0.f;

    // ---- A cp.async coords: 2 x 16B per thread per chunk ----
    const float* Ag = g_c3p + (size_t)p0 * DIMS;
    uint32_t cpdst[2];
    const float* cpsrc[2];
#pragma unroll
    for (int it = 0; it < 2; it++) {
        int idx = tid + it * THREADS;
        int row = idx >> 3, seg = idx & 7;
        cpdst[it] = row * 128 + ((seg ^ (row & 7)) << 4);
        cpsrc[it] = Ag + (size_t)row * DIMS + seg * 4;
    }
    auto cp_chunk = [&](int c, int stage) {
        const uint32_t s = sb + stage * STAGE_BYTES;
        const int k0 = c * KC;
#pragma unroll
        for (int it = 0; it < 2; it++)
            cp16(s + cpdst[it], cpsrc[it] + k0);
    };

    // ---- B fragment pointer (uint4 granularity); 4 n-slots per warp ----
    const uint4* bptr = (const uint4*)g_relf
                      + ((size_t)(b0 >> 3) + warpN * 4) * 512 + lane;

    // ---- LDSM per-msl addressing ----
    int aoff[4], axor[4];
#pragma unroll
    for (int msl = 0; msl < 4; msl++) {
        int rowA = warpM * 64 + msl * 16 + ((lane >> 3) & 1) * 8 + (lane & 7);
        aoff[msl] = rowA * 128;
        axor[msl] = rowA & 7;
    }
    const int kcA = (lane >> 4) & 1;

    float acc[4][4][4];
#pragma unroll
    for (int m = 0; m < 4; m++)
#pragma unroll
        for (int n = 0; n < 4; n++)
#pragma unroll
            for (int r = 0; r < 4; r++) acc[m][n][r] = 0.f;

    uint4 Bb[4];

    // prologue: 3 stages in flight
    cp_chunk(0, 0); CP_COMMIT();
    cp_chunk(1, 1); CP_COMMIT();
    cp_chunk(2, 2); CP_COMMIT();

#define COMPUTE_KP(As, KSBASE)                                                \
    do {                                                                      \
        _Pragma("unroll")                                                     \
        for (int ks2 = 0; ks2 < 2; ++ks2) {                                   \
            const int ks = (KSBASE) + ks2;                                    \
            uint32_t a[4][4];                                                 \
            _Pragma("unroll")                                                 \
            for (int msl = 0; msl < 4; ++msl)                                 \
                LDSM4(a[msl], (As) + aoff[msl] +                              \
                      ((((ks << 1) | kcA) ^ axor[msl]) << 4));                \
            _Pragma("unroll")                                                 \
            for (int nsl = 0; nsl < 4; ++nsl) {                               \
                uint32_t b0v = ks2 ? Bb[nsl].z : Bb[nsl].x;                   \
                uint32_t b1v = ks2 ? Bb[nsl].w : Bb[nsl].y;                   \
                _Pragma("unroll")                                             \
                for (int msl = 0; msl < 4; ++msl)                             \
                    MMA_TF32(acc[msl][nsl], a[msl][0], a[msl][1],             \
                             a[msl][2], a[msl][3], b0v, b1v);                 \
            }                                                                 \
        }                                                                     \
    } while (0)

    for (int cc = 0; cc < NCHUNK; ++cc) {
        CP_WAIT2();
        __syncthreads();
        if (cc + 3 < NCHUNK) cp_chunk(cc + 3, (cc + 3) & 3);
        CP_COMMIT();

        const uint32_t As = sb + (cc & 3) * STAGE_BYTES;
        const int s0 = 2 * cc;

#pragma unroll
        for (int nsl = 0; nsl < 4; nsl++)
            Bb[nsl] = __ldg(bptr + nsl * 512 + s0 * 32);
        COMPUTE_KP(As, 0);

#pragma unroll
        for (int nsl = 0; nsl < 4; nsl++)
            Bb[nsl] = __ldg(bptr + nsl * 512 + (s0 + 1) * 32);
        COMPUTE_KP(As, 2);
    }

    // ---- epilogue: sred[col] += sum_m D[m,col] * r_i(m)[b] * r_j(m)[b] ----
    const float* wi[4][2];
    const float* wj[4][2];
#pragma unroll
    for (int msl = 0; msl < 4; ++msl)
#pragma unroll
        for (int h = 0; h < 2; ++h) {
            int rloc = warpM * 64 + msl * 16 + h * 8 + g;
            uint32_t pij = g_pairIdx[p0 + rloc];
            wi[msl][h] = g_relT + (size_t)(pij >> 16) * BATCH + b0;
            wj[msl][h] = g_relT + (size_t)(pij & 0xFFFF) * BATCH + b0;
        }

#pragma unroll
    for (int nsl = 0; nsl < 4; ++nsl) {
        const int coln = warpN * 32 + nsl * 8 + tig * 2;
        float s0 = 0.f, s1 = 0.f;
#pragma unroll
        for (int msl = 0; msl < 4; ++msl) {
#pragma unroll
            for (int h = 0; h < 2; ++h) {
                float2 a = *(const float2*)(wi[msl][h] + coln);
                float2 b = *(const float2*)(wj[msl][h] + coln);
                s0 += acc[msl][nsl][2 * h]     * a.x * b.x;
                s1 += acc[msl][nsl][2 * h + 1] * a.y * b.y;
            }
        }
#pragma unroll
        for (int o = 4; o <= 16; o <<= 1) {
            s0 += __shfl_xor_sync(0xFFFFFFFFu, s0, o);
            s1 += __shfl_xor_sync(0xFFFFFFFFu, s1, o);
        }
        if (g == 0) {
            atomicAdd(&sred[coln],     s0);
            atomicAdd(&sred[coln + 1], s1);
        }
    }
    __syncthreads();

    if (tid < BN) atomicAdd(out + b0 + tid, sred[tid]);
}

// ---------------------------------------------------------------------------
extern "C" void kernel_launch(void* const* d_in, const int* in_sizes, int n_in,
                              void* d_out, int out_size) {
    const float* x       = (const float*)d_in[0];
    const float* offsets = (const float*)d_in[1];
    const float* coeff0  = (const float*)d_in[2];
    const float* coeff1  = (const float*)d_in[3];
    const float* coeff2  = (const float*)d_in[4];
    const float* coeff3  = (const float*)d_in[5];
    float* out = (float*)d_out;

    cudaFuncSetAttribute(taylor_mma_kernel,
                         cudaFuncAttributeMaxDynamicSharedMemorySize, SMEM_BYTES);

    prep_rel_kernel<<<((DIMS + 1) * BATCH) / 256, 256>>>(x, offsets);
    init_out_kernel<<<BATCH / 256, 256>>>(coeff0, out);

    dim3 pgrid(256, 258);
    pack_kernel<<<pgrid, 64>>>(coeff3, coeff2, coeff1);

    dim3 grid(NROWS / BM, BATCH / BN);   // (260, 8)
    taylor_mma_kernel<<<grid, THREADS, SMEM_BYTES>>>(out);
}

// round 10
// speedup vs baseline: 2.0418x; 1.0962x over previous
#include <cuda_runtime.h>
#include <cstdint>

#define DIMS   256
#define BATCH  2048
#define NPAIR  32896              // 256*257/2 upper-triangle pairs
#define NROWS  33280              // 260 tiles * 128 rows
#define BM     128
#define BN     256
#define THREADS 512
#define STAGE_BYTES (BM * 128 * 4)               // 64 KB: K=128 half, 4 sub-tiles
#define SMEM_BYTES  (2 * STAGE_BYTES + BN * 4)   // 129 KB

// ---- device scratch (allocation-free) ----
__device__ float    g_c3p[NROWS * DIMS];         // 34 MB packed A, row-major, tf32-rounded
__device__ uint32_t g_pairIdx[NROWS];            // (i<<16)|j per row
// B fragment-major: word = ((ng*16 + kp)*32 + lane)*4 + r
//   ng=b>>3, kp=k>>4, lane=(b&7)*4+(k&3), r=((k>>3)&1)*2+((k&7)>>2)
__device__ float    g_relf[BATCH * DIMS];        // 2 MB, tf32-rounded
__device__ float    g_relT[(DIMS + 1) * BATCH];  // rel^T exact; row 256 = 1.0

static __device__ __forceinline__ float f2tf32f(float f) {
    uint32_t r;
    asm("cvt.rna.tf32.f32 %0, %1;" : "=r"(r) : "f"(f));
    return __uint_as_float(r);
}

#define MMA_TF32(C, A0, A1, A2, A3, B0, B1)                                   \
    asm volatile(                                                             \
        "mma.sync.aligned.m16n8k8.row.col.f32.tf32.tf32.f32 "                 \
        "{%0,%1,%2,%3}, {%4,%5,%6,%7}, {%8,%9}, {%0,%1,%2,%3};"               \
        : "+f"((C)[0]), "+f"((C)[1]), "+f"((C)[2]), "+f"((C)[3])              \
        : "r"(A0), "r"(A1), "r"(A2), "r"(A3), "r"(B0), "r"(B1))

#define LDSM4(R, addr)                                                        \
    asm volatile("ldmatrix.sync.aligned.m8n8.x4.shared.b16 {%0,%1,%2,%3}, [%4];" \
        : "=r"((R)[0]), "=r"((R)[1]), "=r"((R)[2]), "=r"((R)[3])              \
        : "r"(addr))

static __device__ __forceinline__ void cp16(uint32_t dst, const void* gsrc) {
    asm volatile("cp.async.cg.shared.global [%0], [%1], 16;"
                 :: "r"(dst), "l"(gsrc) : "memory");
}
#define CP_COMMIT() asm volatile("cp.async.commit_group;" ::: "memory")
#define CP_WAIT(n)  asm volatile("cp.async.wait_group %0;" :: "n"(n) : "memory")

static __device__ __forceinline__ uint32_t smem_u32(const void* p) {
    uint32_t a;
    asm("{ .reg .u64 t; cvta.to.shared.u64 t, %1; cvt.u32.u64 %0, t; }" : "=r"(a) : "l"(p));
    return a;
}

// ---------------------------------------------------------------------------
__global__ void prep_rel_kernel(const float* __restrict__ x,
                                const float* __restrict__ offsets) {
    int idx = blockIdx.x * blockDim.x + threadIdx.x;   // k*BATCH + b
    int k = idx / BATCH;
    int b = idx % BATCH;
    if (k < DIMS) {
        float r = x[b * DIMS + k] - offsets[k];
        g_relT[idx] = r;
        int ng = b >> 3, kp = k >> 4;
        int lane = (b & 7) * 4 + (k & 3);
        int rr = (((k >> 3) & 1) << 1) | ((k & 7) >> 2);
        ((uint32_t*)g_relf)[((ng * 16 + kp) * 32 + lane) * 4 + rr] =
            __float_as_uint(f2tf32f(r));
    } else {
        g_relT[idx] = 1.0f;
    }
}

__global__ void init_out_kernel(const float* __restrict__ c0p,
                                float* __restrict__ out) {
    int b = blockIdx.x * blockDim.x + threadIdx.x;
    if (b < BATCH) out[b] = c0p[0];
}

// ---------------------------------------------------------------------------
// Pack (coalesced): row-major symmetrized A + pair index table.
// ---------------------------------------------------------------------------
__global__ void pack_kernel(const float* __restrict__ c3,
                            const float* __restrict__ c2,
                            const float* __restrict__ c1) {
    int j = blockIdx.x, i = blockIdx.y, t = threadIdx.x;
    int p;
    float4 v;
    uint32_t pidx;
    if (i < 256) {
        if (j < i) return;
        p = i * 256 - (i * (i - 1)) / 2 + (j - i);
        v = *(const float4*)(c3 + ((size_t)(i * 256 + j)) * DIMS + t * 4);
        if (i != j) {
            float4 w = *(const float4*)(c3 + ((size_t)(j * 256 + i)) * DIMS + t * 4);
            v.x += w.x; v.y += w.y; v.z += w.z; v.w += w.w;
        }
        pidx = ((uint32_t)i << 16) | (uint32_t)j;
    } else if (i == 256) {
        p = NPAIR + j;
        v = *(const float4*)(c2 + (size_t)j * DIMS + t * 4);
        pidx = (256u << 16) | (uint32_t)j;
    } else {
        if (j == 0) {
            p = NPAIR + 256;
            v = *(const float4*)(c1 + t * 4);
        } else if (j < 128) {
            p = NPAIR + 256 + j;
            v = make_float4(0.f, 0.f, 0.f, 0.f);
        } else return;
        pidx = (256u << 16) | 256u;
    }
    v.x = f2tf32f(v.x); v.y = f2tf32f(v.y); v.z = f2tf32f(v.z); v.w = f2tf32f(v.w);
    *(float4*)(g_c3p + (size_t)p * DIMS + t * 4) = v;
    if (t == 0) g_pairIdx[p] = pidx;
}

// ---------------------------------------------------------------------------
// Main: 512 threads, 16 warps = 2M x 8N (64x32 warp tiles).
// A: cp.async, 2 stages of K=128 (4 sub-tiles each) -> only 2 barriers total.
// B: direct GMEM fragment loads, one k16 ahead.
// ---------------------------------------------------------------------------
__global__ void __launch_bounds__(THREADS) taylor_mma_kernel(
    float* __restrict__ out) {

    extern __shared__ char smem[];
    const uint32_t sb = smem_u32(smem);
    float* sred = (float*)(smem + 2 * STAGE_BYTES);

    const int tid  = threadIdx.x;
    const int lane = tid & 31, wid = tid >> 5;
    const int warpM = wid & 1, warpN = wid >> 1;   // 2 x 8 warps
    const int g = lane >> 2, tig = lane & 3;
    const int p0 = blockIdx.x * BM;
    const int b0 = blockIdx.y * BN;

    if (tid < BN) sred[tid] = 0.f;

    // ---- A cp.async coords (16KB sub-tile with 512 thr => 2 cp16/thread) ----
    const float* Ag = g_c3p + (size_t)p0 * DIMS;
    uint32_t cpdst[2];
    const float* cpsrc[2];
#pragma unroll
    for (int it = 0; it < 2; it++) {
        int idx = tid + it * THREADS;
        int row = idx >> 3, seg = idx & 7;
        cpdst[it] = row * 128 + ((seg ^ (row & 7)) << 4);
        cpsrc[it] = Ag + (size_t)row * DIMS + seg * 4;
    }
    // stage = 0/1 (K half), q = sub-tile (32 k)
    auto cp_stage = [&](int stage) {
        const uint32_t s = sb + stage * STAGE_BYTES;
#pragma unroll
        for (int q = 0; q < 4; q++) {
            const int k0 = stage * 128 + q * 32;
#pragma unroll
            for (int it = 0; it < 2; it++)
                cp16(s + q * 16384 + cpdst[it], cpsrc[it] + k0);
        }
    };

    // ---- B fragment pointer; 4 n-slots per warp ----
    const uint4* bptr = (const uint4*)g_relf
                      + ((size_t)(b0 >> 3) + warpN * 4) * 512 + lane;

    // ---- LDSM addressing (within a 16KB sub-tile) ----
    int aoff[4], axor[4];
#pragma unroll
    for (int msl = 0; msl < 4; msl++) {
        int rowA = warpM * 64 + msl * 16 + ((lane >> 3) & 1) * 8 + (lane & 7);
        aoff[msl] = rowA * 128;
        axor[msl] = rowA & 7;
    }
    const int kcA = (lane >> 4) & 1;

    float acc[4][4][4];
#pragma unroll
    for (int m = 0; m < 4; m++)
#pragma unroll
        for (int n = 0; n < 4; n++)
#pragma unroll
            for (int r = 0; r < 4; r++) acc[m][n][r] = 0.f;

    uint4 Bb0[4], Bb1[4];

    // prologue: both K halves in flight
    cp_stage(0); CP_COMMIT();
    cp_stage(1); CP_COMMIT();

#define LDB(BB, kp)                                                           \
    do {                                                                      \
        _Pragma("unroll")                                                     \
        for (int nsl = 0; nsl < 4; nsl++)                                     \
            (BB)[nsl] = __ldg(bptr + nsl * 512 + (kp) * 32);                  \
    } while (0)

#define COMPUTE_KP(As, KSBASE, BB)                                            \
    do {                                                                      \
        _Pragma("unroll")                                                     \
        for (int ks2 = 0; ks2 < 2; ++ks2) {                                   \
            const int ks = (KSBASE) + ks2;                                    \
            uint32_t a[4][4];                                                 \
            _Pragma("unroll")                                                 \
            for (int msl = 0; msl < 4; ++msl)                                 \
                LDSM4(a[msl], (As) + aoff[msl] +                              \
                      ((((ks << 1) | kcA) ^ axor[msl]) << 4));                \
            _Pragma("unroll")                                                 \
            for (int nsl = 0; nsl < 4; ++nsl) {                               \
                uint32_t b0v = ks2 ? (BB)[nsl].z : (BB)[nsl].x;               \
                uint32_t b1v = ks2 ? (BB)[nsl].w : (BB)[nsl].y;               \
                _Pragma("unroll")                                             \
                for (int msl = 0; msl < 4; ++msl)                             \
                    MMA_TF32(acc[msl][nsl], a[msl][0], a[msl][1],             \
                             a[msl][2], a[msl][3], b0v, b1v);                 \
            }                                                                 \
        }                                                                     \
    } while (0)

    LDB(Bb0, 0);
    CP_WAIT(1);
    __syncthreads();                       // barrier #1: stage 0 resident

#pragma unroll
    for (int stage = 0; stage < 2; ++stage) {
        const uint32_t S = sb + stage * STAGE_BYTES;
#pragma unroll
        for (int q = 0; q < 4; ++q) {
            const uint32_t As = S + q * 16384;
            const int kp = stage * 8 + q * 2;
            LDB(Bb1, kp + 1);
            COMPUTE_KP(As, 0, Bb0);
            if (kp + 2 < 16) LDB(Bb0, kp + 2);
            COMPUTE_KP(As, 2, Bb1);
        }
        if (stage == 0) {
            CP_WAIT(0);
            __syncthreads();               // barrier #2: stage 1 resident
        }
    }

    // ---- epilogue: sred[col] += sum_m D[m,col] * r_i(m)[b] * r_j(m)[b] ----
    const float* wi[4][2];
    const float* wj[4][2];
#pragma unroll
    for (int msl = 0; msl < 4; ++msl)
#pragma unroll
        for (int h = 0; h < 2; ++h) {
            int rloc = warpM * 64 + msl * 16 + h * 8 + g;
            uint32_t pij = g_pairIdx[p0 + rloc];
            wi[msl][h] = g_relT + (size_t)(pij >> 16) * BATCH + b0;
            wj[msl][h] = g_relT + (size_t)(pij & 0xFFFF) * BATCH + b0;
        }

#pragma unroll
    for (int nsl = 0; nsl < 4; ++nsl) {
        const int coln = warpN * 32 + nsl * 8 + tig * 2;
        float s0 = 0.f, s1 = 0.f;
#pragma unroll
        for (int msl = 0; msl < 4; ++msl) {
#pragma unroll
            for (int h = 0; h < 2; ++h) {
                float2 a = *(const float2*)(wi[msl][h] + coln);
                float2 b = *(const float2*)(wj[msl][h] + coln);
                s0 += acc[msl][nsl][2 * h]     * a.x * b.x;
                s1 += acc[msl][nsl][2 * h + 1] * a.y * b.y;
            }
        }
#pragma unroll
        for (int o = 4; o <= 16; o <<= 1) {
            s0 += __shfl_xor_sync(0xFFFFFFFFu, s0, o);
            s1 += __shfl_xor_sync(0xFFFFFFFFu, s1, o);
        }
        if (g == 0) {
            atomicAdd(&sred[coln],     s0);
            atomicAdd(&sred[coln + 1], s1);
        }
    }
    __syncthreads();

    if (tid < BN) atomicAdd(out + b0 + tid, sred[tid]);
}

// ---------------------------------------------------------------------------
extern "C" void kernel_launch(void* const* d_in, const int* in_sizes, int n_in,
                              void* d_out, int out_size) {
    const float* x       = (const float*)d_in[0];
    const float* offsets = (const float*)d_in[1];
    const float* coeff0  = (const float*)d_in[2];
    const float* coeff1  = (const float*)d_in[3];
    const float* coeff2  = (const float*)d_in[4];
    const float* coeff3  = (const float*)d_in[5];
    float* out = (float*)d_out;

    cudaFuncSetAttribute(taylor_mma_kernel,
                         cudaFuncAttributeMaxDynamicSharedMemorySize, SMEM_BYTES);

    prep_rel_kernel<<<((DIMS + 1) * BATCH) / 256, 256>>>(x, offsets);
    init_out_kernel<<<BATCH / 256, 256>>>(coeff0, out);

    dim3 pgrid(256, 258);
    pack_kernel<<<pgrid, 64>>>(coeff3, coeff2, coeff1);

    dim3 grid(NROWS / BM, BATCH / BN);   // (260, 8)
    taylor_mma_kernel<<<grid, THREADS, SMEM_BYTES>>>(out);
}